// round 1
// baseline (speedup 1.0000x reference)
#include <cuda_runtime.h>
#include <cuda_bf16.h>

#define D      1024
#define BS     80
#define NB     16      // batch
#define STEPN  5
#define ALPHA  0.01f
#define KSPLIT 8
#define QS     72      // q_tile row stride (floats): 5*72 mod 32 banks = 8 -> conflict-free
#define WS     40      // w_tile row stride (floats): 160B, 16B aligned

// scratch (no device alloc allowed)
__device__ __align__(16) float g_q[BS * D];
__device__ __align__(16) float g_part[KSPLIT * BS * D];
__device__ __align__(16) float g_y[BS * D];
__device__ __align__(16) float g_mu[D];
__device__ __align__(16) float g_rstd[D];

// ---------------------------------------------------------------------------
// K1: q[n,i] via linear-readout recurrence.
//   b = n % 16, s = n / 16 (step-major mem), readout vector = x row n (batch-major)
//   d_t = x[b*5+t] . x[n];  g <- g*(1 - a*xt^2) + xt*(a*d_t), t = 0..s
// ---------------------------------------------------------------------------
__global__ void k1_qcompute(const float* __restrict__ x) {
    const int n = blockIdx.x;
    const int b = n % NB;
    const int s = n / NB;
    const int rb = b * STEPN;
    const int tid = threadIdx.x;

    __shared__ float sred[STEPN][8];
    __shared__ float sd[STEPN];

    float pd[STEPN] = {0.f, 0.f, 0.f, 0.f, 0.f};
    const float* xn = x + n * D;
    for (int j = tid; j < D; j += 256) {
        float v = xn[j];
#pragma unroll
        for (int t = 0; t < STEPN; t++)
            pd[t] += x[(rb + t) * D + j] * v;
    }
#pragma unroll
    for (int t = 0; t < STEPN; t++) {
        float v = pd[t];
#pragma unroll
        for (int o = 16; o > 0; o >>= 1)
            v += __shfl_down_sync(0xffffffffu, v, o);
        if ((tid & 31) == 0) sred[t][tid >> 5] = v;
    }
    __syncthreads();
    if (tid < STEPN) {
        float v = 0.f;
#pragma unroll
        for (int w = 0; w < 8; w++) v += sred[tid][w];
        sd[tid] = ALPHA * v;   // fold alpha into d_t
    }
    __syncthreads();

    for (int i = tid; i < D; i += 256) {
        float g = 0.f;
        for (int t = 0; t <= s; t++) {
            float xv = x[(rb + t) * D + i];
            g = g * (1.f - ALPHA * xv * xv) + xv * sd[t];
        }
        g_q[n * D + i] = g;
    }
}

// ---------------------------------------------------------------------------
// K2: partial GEMM  part[ks][n,k] = sum_{j in chunk ks} q[n,j] * W[k,j]
// Block tile: all 80 rows x 32 cols, j-chunk of 128 (2 sub-tiles of 64).
// 128 threads: rg = tid/8 (16 row-groups x 5 rows), cg = tid%8 (x 4 cols).
// ---------------------------------------------------------------------------
__global__ void __launch_bounds__(128) k2_gemm(const float* __restrict__ W) {
    __shared__ float q_tile[BS * QS];
    __shared__ float w_tile[64 * WS];

    const int tid = threadIdx.x;
    const int cT  = blockIdx.x * 32;
    const int j0  = blockIdx.y * 128;
    const int rg  = tid >> 3;   // 0..15
    const int cg  = tid & 7;    // 0..7

    float acc[5][4];
#pragma unroll
    for (int m = 0; m < 5; m++)
#pragma unroll
        for (int c = 0; c < 4; c++) acc[m][c] = 0.f;

    for (int sc = 0; sc < 2; sc++) {
        const int jj0 = j0 + sc * 64;
        // load q sub-tile [80 x 64] (float4, coalesced)
        for (int t = tid; t < BS * 16; t += 128) {
            int r = t >> 4, v = t & 15;
            float4 val = *(const float4*)(g_q + r * D + jj0 + v * 4);
            *(float4*)(q_tile + r * QS + v * 4) = val;
        }
        // load W sub-tile transposed: w_tile[jj][c] = W[cT+c][jj0+jj]
        for (int t = tid; t < 32 * 64; t += 128) {
            int c = t >> 6, jj = t & 63;
            w_tile[jj * WS + c] = W[(cT + c) * D + jj0 + jj];
        }
        __syncthreads();

#pragma unroll 4
        for (int jj = 0; jj < 64; jj += 4) {
            float4 qv[5];
#pragma unroll
            for (int m = 0; m < 5; m++)
                qv[m] = *(const float4*)(q_tile + (rg * 5 + m) * QS + jj);
#pragma unroll
            for (int d2 = 0; d2 < 4; d2++) {
                float4 wv = *(const float4*)(w_tile + (jj + d2) * WS + cg * 4);
#pragma unroll
                for (int m = 0; m < 5; m++) {
                    float qc = (d2 == 0) ? qv[m].x : (d2 == 1) ? qv[m].y
                             : (d2 == 2) ? qv[m].z : qv[m].w;
                    acc[m][0] += qc * wv.x;
                    acc[m][1] += qc * wv.y;
                    acc[m][2] += qc * wv.z;
                    acc[m][3] += qc * wv.w;
                }
            }
        }
        __syncthreads();
    }

    float* outp = g_part + blockIdx.y * (BS * D);
#pragma unroll
    for (int m = 0; m < 5; m++) {
        float4 v = make_float4(acc[m][0], acc[m][1], acc[m][2], acc[m][3]);
        *(float4*)(outp + (rg * 5 + m) * D + cT + cg * 4) = v;
    }
}

// ---------------------------------------------------------------------------
// K3a: reduce K-split partials + bias -> y; per-column BN stats (biased var)
// 1024 threads total (grid 4 x 256), one column each.
// ---------------------------------------------------------------------------
__global__ void k3a_stats(const float* __restrict__ bias) {
    const int k = blockIdx.x * blockDim.x + threadIdx.x;
    const float bk = bias[k];
    float sum = 0.f, sumsq = 0.f;
    for (int n = 0; n < BS; n++) {
        float v = bk;
#pragma unroll
        for (int p = 0; p < KSPLIT; p++)
            v += g_part[p * (BS * D) + n * D + k];
        g_y[n * D + k] = v;
        sum += v;
        sumsq += v * v;
    }
    float m = sum * (1.f / BS);
    float var = sumsq * (1.f / BS) - m * m;
    g_mu[k] = m;
    g_rstd[k] = rsqrtf(var + 1e-5f);
}

// ---------------------------------------------------------------------------
// K3b: per-row relu(BN * gamma + beta) then L2-normalize. One block per row.
// ---------------------------------------------------------------------------
__global__ void k3b_norm(const float* __restrict__ gamma,
                         const float* __restrict__ beta,
                         float* __restrict__ out) {
    const int n = blockIdx.x;
    const int tid = threadIdx.x;
    const int k0 = tid * 4;

    float4 y4  = *(const float4*)(g_y + n * D + k0);
    float4 mu4 = *(const float4*)(g_mu + k0);
    float4 rs4 = *(const float4*)(g_rstd + k0);
    float4 ga4 = *(const float4*)(gamma + k0);
    float4 be4 = *(const float4*)(beta + k0);

    float z0 = fmaxf((y4.x - mu4.x) * rs4.x * ga4.x + be4.x, 0.f);
    float z1 = fmaxf((y4.y - mu4.y) * rs4.y * ga4.y + be4.y, 0.f);
    float z2 = fmaxf((y4.z - mu4.z) * rs4.z * ga4.z + be4.z, 0.f);
    float z3 = fmaxf((y4.w - mu4.w) * rs4.w * ga4.w + be4.w, 0.f);

    float ss = z0 * z0 + z1 * z1 + z2 * z2 + z3 * z3;
#pragma unroll
    for (int o = 16; o > 0; o >>= 1)
        ss += __shfl_down_sync(0xffffffffu, ss, o);

    __shared__ float sr[8];
    __shared__ float stot;
    if ((tid & 31) == 0) sr[tid >> 5] = ss;
    __syncthreads();
    if (tid == 0) {
        float t = 0.f;
#pragma unroll
        for (int w = 0; w < 8; w++) t += sr[w];
        stot = 1.f / fmaxf(sqrtf(t), 1e-12f);
    }
    __syncthreads();
    float sc = stot;

    float4 o4 = make_float4(z0 * sc, z1 * sc, z2 * sc, z3 * sc);
    *(float4*)(out + n * D + k0) = o4;
}

// ---------------------------------------------------------------------------
extern "C" void kernel_launch(void* const* d_in, const int* in_sizes, int n_in,
                              void* d_out, int out_size) {
    (void)in_sizes; (void)n_in; (void)out_size;
    const float* x     = (const float*)d_in[0];
    const float* W     = (const float*)d_in[1];
    const float* bias  = (const float*)d_in[2];
    const float* gamma = (const float*)d_in[3];
    const float* beta  = (const float*)d_in[4];
    float* out = (float*)d_out;

    k1_qcompute<<<BS, 256>>>(x);
    k2_gemm<<<dim3(D / 32, KSPLIT), 128>>>(W);
    k3a_stats<<<D / 256, 256>>>(bias);
    k3b_norm<<<BS, 256>>>(gamma, beta, out);
}

// round 2
// speedup vs baseline: 1.6116x; 1.6116x over previous
#include <cuda_runtime.h>

#define D      1024
#define BS     80
#define NBATCH 16
#define STEPN  5
#define ALPHA  0.01f
#define NBLK   128
#define NTHR   256

// ---- global scratch (no device alloc allowed) ----
__device__ __align__(16) float g_q[BS * D];
__device__ __align__(16) float g_y[BS * D];
__device__ __align__(16) float g_csum[2][D];
__device__ __align__(16) float g_csq[2][D];
__device__ unsigned g_bar0, g_bar1, g_depart;

// ---- packed fp32x2 helpers (sm_103a FFMA2) ----
__device__ __forceinline__ unsigned long long pack2(float v) {
    unsigned long long r;
    asm("mov.b64 %0, {%1, %1};" : "=l"(r) : "f"(v));
    return r;
}
__device__ __forceinline__ void ffma2(unsigned long long& acc,
                                      unsigned long long a,
                                      unsigned long long b) {
    asm("fma.rn.f32x2 %0, %1, %2, %0;" : "+l"(acc) : "l"(a), "l"(b));
}

// ---- software grid barrier (single-wave grid; replay-safe via depart reset) ----
__device__ __forceinline__ void gridbar(unsigned* cnt) {
    __syncthreads();
    if (threadIdx.x == 0) {
        __threadfence();
        atomicAdd(cnt, 1u);
        while (*(volatile unsigned*)cnt < NBLK) { }
        __threadfence();
    }
    __syncthreads();
}

__global__ void __launch_bounds__(NTHR)
fused_kernel(const float* __restrict__ x, const float* __restrict__ W,
             const float* __restrict__ bias, const float* __restrict__ gamma,
             const float* __restrict__ beta, float* __restrict__ out) {
    // gemm view: q_tile 40x132 (5280) + w_tile 128x20 (2560) = 7840 floats
    // reduce view (aliased): accbuf 8*32*20 (5120) + ys 40*16 (640)
    __shared__ __align__(16) float sm[7840];
    __shared__ float sred[STEPN][8];
    __shared__ float sd[STEPN];
    __shared__ float s_r[8];
    __shared__ float s_tot;

    const int tid = threadIdx.x;
    const int bid = blockIdx.x;

    // ================= phase 1: q rows (blocks 0..79) =================
    if (bid < BS) {
        const int n = bid;
        const int b = n % NBATCH;
        const int s = n / NBATCH;
        const int rb = b * STEPN;

        float pd[STEPN] = {0.f, 0.f, 0.f, 0.f, 0.f};
        const float* xn = x + n * D;
        for (int j = tid; j < D; j += NTHR) {
            float v = xn[j];
#pragma unroll
            for (int t = 0; t < STEPN; t++)
                pd[t] += x[(rb + t) * D + j] * v;
        }
#pragma unroll
        for (int t = 0; t < STEPN; t++) {
            float v = pd[t];
#pragma unroll
            for (int o = 16; o > 0; o >>= 1)
                v += __shfl_down_sync(0xffffffffu, v, o);
            if ((tid & 31) == 0) sred[t][tid >> 5] = v;
        }
        __syncthreads();
        if (tid < STEPN) {
            float v = 0.f;
#pragma unroll
            for (int w = 0; w < 8; w++) v += sred[tid][w];
            sd[tid] = ALPHA * v;
        }
        __syncthreads();
        for (int i = tid; i < D; i += NTHR) {
            float g = 0.f;
            for (int t = 0; t <= s; t++) {
                float xv = x[(rb + t) * D + i];
                g = g * (1.f - ALPHA * xv * xv) + xv * sd[t];
            }
            g_q[n * D + i] = g;
        }
    }

    gridbar(&g_bar0);

    // ================= phase 2: GEMM + col-stat partials =================
    // block tile: rows [r0, r0+40) x cols [c0, c0+16), full K, in-block K-split x8
    {
        float* q_tile = sm;            // [40][132]
        float* w_tile = sm + 40 * 132; // [128][20]

        const int rh = bid >> 6;        // 0..1
        const int r0 = rh * 40;
        const int c0 = (bid & 63) * 16;
        const int kq = tid >> 5;        // warp = K-chunk slice (16 ks of 128)
        const int lane = tid & 31;
        const int rg = lane >> 2;       // 8 row-groups x 5 rows
        const int cq = lane & 3;        // 4 col-quads x 4 cols

        unsigned long long acc[5][2];
#pragma unroll
        for (int m = 0; m < 5; m++) { acc[m][0] = 0ull; acc[m][1] = 0ull; }

        for (int ch = 0; ch < 8; ch++) {
            const int kb = ch * 128;
            // load q sub-tile [40 x 128] (float4, coalesced)
#pragma unroll
            for (int t = tid; t < 40 * 32; t += NTHR) {
                int r = t >> 5, v = t & 31;
                float4 qv = *(const float4*)(g_q + (r0 + r) * D + kb + v * 4);
                *(float4*)(q_tile + r * 132 + v * 4) = qv;
            }
            // load W sub-tile transposed: w_tile[k][c] = W[c0+c][kb+k]
#pragma unroll
            for (int t = tid; t < 16 * 32; t += NTHR) {
                int c = t >> 5, v = t & 31;
                float4 wv = *(const float4*)(W + (c0 + c) * D + kb + v * 4);
                w_tile[(v * 4 + 0) * 20 + c] = wv.x;
                w_tile[(v * 4 + 1) * 20 + c] = wv.y;
                w_tile[(v * 4 + 2) * 20 + c] = wv.z;
                w_tile[(v * 4 + 3) * 20 + c] = wv.w;
            }
            __syncthreads();

            const float* qb = q_tile + rg * 5 * 132 + kq * 16;
            const float* wb = w_tile + kq * 16 * 20 + cq * 4;
#pragma unroll
            for (int k2 = 0; k2 < 16; k2 += 2) {
                float2 qv[5];
#pragma unroll
                for (int m = 0; m < 5; m++)
                    qv[m] = *(const float2*)(qb + m * 132 + k2);
                ulonglong2 wv0 = *(const ulonglong2*)(wb + k2 * 20);
                ulonglong2 wv1 = *(const ulonglong2*)(wb + (k2 + 1) * 20);
#pragma unroll
                for (int m = 0; m < 5; m++) {
                    unsigned long long ql = pack2(qv[m].x);
                    unsigned long long qh = pack2(qv[m].y);
                    ffma2(acc[m][0], ql, wv0.x);
                    ffma2(acc[m][1], ql, wv0.y);
                    ffma2(acc[m][0], qh, wv1.x);
                    ffma2(acc[m][1], qh, wv1.y);
                }
            }
            __syncthreads();
        }

        // stage per-warp partials (aliases q_tile, dead now)
        float* accbuf = sm;            // [8][32][20]
        float* ys = sm + 5120;         // [40][16]
        {
            unsigned long long* dst =
                (unsigned long long*)(accbuf + (kq * 32 + lane) * 20);
#pragma unroll
            for (int m = 0; m < 5; m++) {
                dst[m * 2]     = acc[m][0];
                dst[m * 2 + 1] = acc[m][1];
            }
        }
        __syncthreads();

        // reduce K-split, add bias, write y
#pragma unroll
        for (int t = tid; t < 640; t += NTHR) {
            int slot = t / 20, v = t - slot * 20;
            float ssum = 0.f;
#pragma unroll
            for (int p = 0; p < 8; p++)
                ssum += accbuf[p * 640 + slot * 20 + v];
            int rgs = slot >> 2, cqs = slot & 3;
            int m = v >> 2, cc = v & 3;
            int row = rgs * 5 + m;
            int col = cqs * 4 + cc;
            float yv = ssum + bias[c0 + col];
            g_y[(r0 + row) * D + c0 + col] = yv;
            ys[row * 16 + col] = yv;
        }
        __syncthreads();

        // per-column partial stats over this block's 40 rows
        if (tid < 16) {
            float su = 0.f, sq = 0.f;
#pragma unroll
            for (int r = 0; r < 40; r++) {
                float v = ys[r * 16 + tid];
                su += v;
                sq += v * v;
            }
            g_csum[rh][c0 + tid] = su;
            g_csq[rh][c0 + tid]  = sq;
        }
    }

    gridbar(&g_bar1);

    // ================= phase 3: BN + relu + row L2-normalize =================
    if (bid < BS) {
        const int n = bid;
        const int k0 = tid * 4;

        float4 y4  = *(const float4*)(g_y + n * D + k0);
        float4 s04 = *(const float4*)(&g_csum[0][k0]);
        float4 s14 = *(const float4*)(&g_csum[1][k0]);
        float4 q04 = *(const float4*)(&g_csq[0][k0]);
        float4 q14 = *(const float4*)(&g_csq[1][k0]);
        float4 ga4 = *(const float4*)(gamma + k0);
        float4 be4 = *(const float4*)(beta + k0);

        const float inv = 1.f / (float)BS;
        float z[4];
        {
            float mu, var, rstd;
            mu = (s04.x + s14.x) * inv; var = (q04.x + q14.x) * inv - mu * mu;
            rstd = rsqrtf(var + 1e-5f);
            z[0] = fmaxf((y4.x - mu) * rstd * ga4.x + be4.x, 0.f);
            mu = (s04.y + s14.y) * inv; var = (q04.y + q14.y) * inv - mu * mu;
            rstd = rsqrtf(var + 1e-5f);
            z[1] = fmaxf((y4.y - mu) * rstd * ga4.y + be4.y, 0.f);
            mu = (s04.z + s14.z) * inv; var = (q04.z + q14.z) * inv - mu * mu;
            rstd = rsqrtf(var + 1e-5f);
            z[2] = fmaxf((y4.z - mu) * rstd * ga4.z + be4.z, 0.f);
            mu = (s04.w + s14.w) * inv; var = (q04.w + q14.w) * inv - mu * mu;
            rstd = rsqrtf(var + 1e-5f);
            z[3] = fmaxf((y4.w - mu) * rstd * ga4.w + be4.w, 0.f);
        }

        float ss = z[0] * z[0] + z[1] * z[1] + z[2] * z[2] + z[3] * z[3];
#pragma unroll
        for (int o = 16; o > 0; o >>= 1)
            ss += __shfl_down_sync(0xffffffffu, ss, o);
        if ((tid & 31) == 0) s_r[tid >> 5] = ss;
        __syncthreads();
        if (tid == 0) {
            float t = 0.f;
#pragma unroll
            for (int w = 0; w < 8; w++) t += s_r[w];
            s_tot = 1.f / fmaxf(sqrtf(t), 1e-12f);
        }
        __syncthreads();
        float sc = s_tot;

        float4 o4 = make_float4(z[0] * sc, z[1] * sc, z[2] * sc, z[3] * sc);
        *(float4*)(out + n * D + k0) = o4;
    }

    // ---- depart + replay-safe reset of barrier state ----
    if (threadIdx.x == 0) {
        __threadfence();
        unsigned old = atomicAdd(&g_depart, 1u);
        if (old == NBLK - 1) {
            g_bar0 = 0;
            g_bar1 = 0;
            __threadfence();
            g_depart = 0;
            __threadfence();
        }
    }
}

extern "C" void kernel_launch(void* const* d_in, const int* in_sizes, int n_in,
                              void* d_out, int out_size) {
    (void)in_sizes; (void)n_in; (void)out_size;
    const float* x     = (const float*)d_in[0];
    const float* W     = (const float*)d_in[1];
    const float* bias  = (const float*)d_in[2];
    const float* gamma = (const float*)d_in[3];
    const float* beta  = (const float*)d_in[4];
    float* out = (float*)d_out;

    fused_kernel<<<NBLK, NTHR>>>(x, W, bias, gamma, beta, out);
}

// round 3
// speedup vs baseline: 2.1667x; 1.3444x over previous
#include <cuda_runtime.h>

#define D      1024
#define BS     80
#define NBATCH 16
#define STEPN  5
#define ALPHA  0.01f
#define NBLK   128
#define NTHR   256

// ---- global scratch (no device alloc allowed) ----
__device__ __align__(16) float g_q[BS * D];
__device__ __align__(16) float g_y[BS * D];
__device__ __align__(16) float g_csum[2][D];
__device__ __align__(16) float g_csq[2][D];
__device__ unsigned g_bar0, g_bar1, g_depart;

// ---- packed fp32x2 helpers (sm_103a) ----
__device__ __forceinline__ void ffma2(unsigned long long& acc,
                                      unsigned long long a,
                                      unsigned long long b) {
    asm("fma.rn.f32x2 %0, %1, %2, %0;" : "+l"(acc) : "l"(a), "l"(b));
}
__device__ __forceinline__ unsigned long long add2(unsigned long long a,
                                                   unsigned long long b) {
    unsigned long long r;
    asm("add.rn.f32x2 %0, %1, %2;" : "=l"(r) : "l"(a), "l"(b));
    return r;
}
__device__ __forceinline__ unsigned long long shfl_xor_u64(unsigned long long v, int m) {
    unsigned lo = (unsigned)v, hi = (unsigned)(v >> 32);
    lo = __shfl_xor_sync(0xffffffffu, lo, m);
    hi = __shfl_xor_sync(0xffffffffu, hi, m);
    return ((unsigned long long)hi << 32) | (unsigned long long)lo;
}

// ---- software grid barrier (single-wave grid; replay-safe via depart reset) ----
__device__ __forceinline__ void gridbar(unsigned* cnt) {
    __syncthreads();
    if (threadIdx.x == 0) {
        __threadfence();
        atomicAdd(cnt, 1u);
        while (*(volatile unsigned*)cnt < NBLK) { }
        __threadfence();
    }
    __syncthreads();
}

__global__ void __launch_bounds__(NTHR, 1)
fused_kernel(const float* __restrict__ x, const float* __restrict__ W,
             const float* __restrict__ bias, const float* __restrict__ gamma,
             const float* __restrict__ beta, float* __restrict__ out) {
    __shared__ __align__(16) float st[128 * 82];   // k-split staging (42KB)
    __shared__ float ys[40 * 16];
    __shared__ float sred[STEPN][8];
    __shared__ float sd[STEPN];
    __shared__ float s_r[8];
    __shared__ float s_tot;

    const int tid = threadIdx.x;
    const int bid = blockIdx.x;

    // ================= phase 1: q rows (blocks 0..79) =================
    if (bid < BS) {
        const int n = bid;
        const int b = n % NBATCH;
        const int s = n / NBATCH;
        const int rb = b * STEPN;

        float pd[STEPN] = {0.f, 0.f, 0.f, 0.f, 0.f};
        const float* xn = x + n * D;
        for (int j = tid; j < D; j += NTHR) {
            float v = xn[j];
#pragma unroll
            for (int t = 0; t < STEPN; t++)
                pd[t] += x[(rb + t) * D + j] * v;
        }
#pragma unroll
        for (int t = 0; t < STEPN; t++) {
            float v = pd[t];
#pragma unroll
            for (int o = 16; o > 0; o >>= 1)
                v += __shfl_down_sync(0xffffffffu, v, o);
            if ((tid & 31) == 0) sred[t][tid >> 5] = v;
        }
        __syncthreads();
        if (tid < STEPN) {
            float v = 0.f;
#pragma unroll
            for (int w = 0; w < 8; w++) v += sred[tid][w];
            sd[tid] = ALPHA * v;
        }
        __syncthreads();
        for (int i = tid; i < D; i += NTHR) {
            float g = 0.f;
            for (int t = 0; t <= s; t++) {
                float xv = x[(rb + t) * D + i];
                g = g * (1.f - ALPHA * xv * xv) + xv * sd[t];
            }
            g_q[n * D + i] = g;
        }
    }

    gridbar(&g_bar0);

    // ================= phase 2: GEMM (register tiles, no smem mainloop) =====
    // block tile: rows [r0, r0+40) x cols [c0, c0+16).
    // thread: 10 rows x 4 cols register tile, 16-way k-split (w:8 x jj:2).
    // f32x2 packs over K (even/odd dual partials, folded in epilogue).
    {
        const int rh = bid >> 6;
        const int r0 = rh * 40;
        const int c0 = (bid & 63) * 16;
        const int w  = tid >> 5;
        const int lane = tid & 31;
        const int sp = lane & 15, jj = lane >> 4;
        const int rg = sp >> 2,  cg = sp & 3;

        const float* qbase = g_q + (r0 + rg * 10) * D + w * 128 + jj * 4;
        const float* wbase = W   + (c0 + cg * 4)  * D + w * 128 + jj * 4;

        unsigned long long acc[4][10];
#pragma unroll
        for (int c = 0; c < 4; c++)
#pragma unroll
            for (int i = 0; i < 10; i++) acc[c][i] = 0ull;

#pragma unroll 4
        for (int t = 0; t < 16; t++) {
            const int ko = t * 8;
            ulonglong2 qv[10];
#pragma unroll
            for (int i = 0; i < 10; i++)
                qv[i] = *(const ulonglong2*)(qbase + i * D + ko);
#pragma unroll
            for (int c = 0; c < 4; c++) {
                ulonglong2 wv = *(const ulonglong2*)(wbase + c * D + ko);
#pragma unroll
                for (int i = 0; i < 10; i++) {
                    ffma2(acc[c][i], qv[i].x, wv.x);
                    ffma2(acc[c][i], qv[i].y, wv.y);
                }
            }
        }

        // intra-warp k-reduce (jj pairs: lane ^ 16)
#pragma unroll
        for (int c = 0; c < 4; c++)
#pragma unroll
            for (int i = 0; i < 10; i++)
                acc[c][i] = add2(acc[c][i], shfl_xor_u64(acc[c][i], 16));

        if (jj == 0) {
            float* dst = st + (w * 16 + sp) * 82;
#pragma unroll
            for (int c = 0; c < 4; c++)
#pragma unroll
                for (int i = 0; i < 10; i++)
                    *(unsigned long long*)(dst + (c * 10 + i) * 2) = acc[c][i];
        }
        __syncthreads();

        // final 8-way warp reduce + bias; write y
        for (int idx = tid; idx < 640; idx += NTHR) {
            const int row = idx >> 4, col = idx & 15;
            const int rg2 = row / 10, ii = row - rg2 * 10;
            const int cg2 = col >> 2, c = col & 3;
            const int slot = rg2 * 4 + cg2;
            const int off = (c * 10 + ii) * 2;
            float lo = 0.f, hi = 0.f;
#pragma unroll
            for (int ww = 0; ww < 8; ww++) {
                float2 v = *(const float2*)(st + (ww * 16 + slot) * 82 + off);
                lo += v.x;
                hi += v.y;
            }
            const float yv = lo + hi + bias[c0 + col];
            g_y[(r0 + row) * D + c0 + col] = yv;
            ys[row * 16 + col] = yv;
        }
        __syncthreads();

        // per-column partial stats over this block's 40 rows
        if (tid < 16) {
            float su = 0.f, sq = 0.f;
#pragma unroll
            for (int r = 0; r < 40; r++) {
                float v = ys[r * 16 + tid];
                su += v;
                sq += v * v;
            }
            g_csum[rh][c0 + tid] = su;
            g_csq[rh][c0 + tid]  = sq;
        }
    }

    gridbar(&g_bar1);

    // ================= phase 3: BN + relu + row L2-normalize =================
    if (bid < BS) {
        const int n = bid;
        const int k0 = tid * 4;

        float4 y4  = *(const float4*)(g_y + n * D + k0);
        float4 s04 = *(const float4*)(&g_csum[0][k0]);
        float4 s14 = *(const float4*)(&g_csum[1][k0]);
        float4 q04 = *(const float4*)(&g_csq[0][k0]);
        float4 q14 = *(const float4*)(&g_csq[1][k0]);
        float4 ga4 = *(const float4*)(gamma + k0);
        float4 be4 = *(const float4*)(beta + k0);

        const float inv = 1.f / (float)BS;
        float z[4];
        {
            float mu, var, rstd;
            mu = (s04.x + s14.x) * inv; var = (q04.x + q14.x) * inv - mu * mu;
            rstd = rsqrtf(var + 1e-5f);
            z[0] = fmaxf((y4.x - mu) * rstd * ga4.x + be4.x, 0.f);
            mu = (s04.y + s14.y) * inv; var = (q04.y + q14.y) * inv - mu * mu;
            rstd = rsqrtf(var + 1e-5f);
            z[1] = fmaxf((y4.y - mu) * rstd * ga4.y + be4.y, 0.f);
            mu = (s04.z + s14.z) * inv; var = (q04.z + q14.z) * inv - mu * mu;
            rstd = rsqrtf(var + 1e-5f);
            z[2] = fmaxf((y4.z - mu) * rstd * ga4.z + be4.z, 0.f);
            mu = (s04.w + s14.w) * inv; var = (q04.w + q14.w) * inv - mu * mu;
            rstd = rsqrtf(var + 1e-5f);
            z[3] = fmaxf((y4.w - mu) * rstd * ga4.w + be4.w, 0.f);
        }

        float ss = z[0] * z[0] + z[1] * z[1] + z[2] * z[2] + z[3] * z[3];
#pragma unroll
        for (int o = 16; o > 0; o >>= 1)
            ss += __shfl_down_sync(0xffffffffu, ss, o);
        if ((tid & 31) == 0) s_r[tid >> 5] = ss;
        __syncthreads();
        if (tid == 0) {
            float t = 0.f;
#pragma unroll
            for (int w = 0; w < 8; w++) t += s_r[w];
            s_tot = 1.f / fmaxf(sqrtf(t), 1e-12f);
        }
        __syncthreads();
        float sc = s_tot;

        float4 o4 = make_float4(z[0] * sc, z[1] * sc, z[2] * sc, z[3] * sc);
        *(float4*)(out + n * D + k0) = o4;
    }

    // ---- depart + replay-safe reset of barrier state ----
    if (threadIdx.x == 0) {
        __threadfence();
        unsigned old = atomicAdd(&g_depart, 1u);
        if (old == NBLK - 1) {
            g_bar0 = 0;
            g_bar1 = 0;
            __threadfence();
            g_depart = 0;
            __threadfence();
        }
    }
}

extern "C" void kernel_launch(void* const* d_in, const int* in_sizes, int n_in,
                              void* d_out, int out_size) {
    (void)in_sizes; (void)n_in; (void)out_size;
    const float* x     = (const float*)d_in[0];
    const float* W     = (const float*)d_in[1];
    const float* bias  = (const float*)d_in[2];
    const float* gamma = (const float*)d_in[3];
    const float* beta  = (const float*)d_in[4];
    float* out = (float*)d_out;

    fused_kernel<<<NBLK, NTHR>>>(x, W, bias, gamma, beta, out);
}

// round 4
// speedup vs baseline: 2.3529x; 1.0860x over previous
#include <cuda_runtime.h>
#include <cstdint>

#define D      1024
#define BS     80
#define NBATCH 16
#define STEPN  5
#define ALPHA  0.01f
#define NBLK   128
#define NTHR   512
#define QW     132            // padded smem row stride (floats)
#define BUF_FL 7392           // (40 + 16) * 132 floats per buffer
#define DYN_FL (2 * BUF_FL)   // two buffers (staging aliases them later)

// ---- global scratch (no device alloc allowed) ----
__device__ __align__(16) float g_q[BS * D];
__device__ __align__(16) float g_y[BS * D];
__device__ __align__(16) float g_csum[2][D];
__device__ __align__(16) float g_csq[2][D];
__device__ unsigned g_bar0, g_bar1, g_depart;

// ---- packed fp32x2 helpers ----
__device__ __forceinline__ void ffma2(unsigned long long& acc,
                                      unsigned long long a,
                                      unsigned long long b) {
    asm("fma.rn.f32x2 %0, %1, %2, %0;" : "+l"(acc) : "l"(a), "l"(b));
}
__device__ __forceinline__ float fold2(unsigned long long v) {
    float lo, hi;
    asm("mov.b64 {%0, %1}, %2;" : "=f"(lo), "=f"(hi) : "l"(v));
    return lo + hi;
}

// ---- cp.async helpers ----
__device__ __forceinline__ void cp_async16(uint32_t saddr, const void* gptr) {
    asm volatile("cp.async.cg.shared.global [%0], [%1], 16;"
                 :: "r"(saddr), "l"(gptr));
}
__device__ __forceinline__ uint32_t s2u(const void* p) {
    return (uint32_t)__cvta_generic_to_shared(p);
}

// ---- software grid barrier (single-wave grid; replay-safe) ----
__device__ __forceinline__ void gridbar(unsigned* cnt) {
    __syncthreads();
    if (threadIdx.x == 0) {
        __threadfence();
        atomicAdd(cnt, 1u);
        while (*(volatile unsigned*)cnt < NBLK) { }
        __threadfence();
    }
    __syncthreads();
}

__global__ void __launch_bounds__(NTHR, 1)
fused_kernel(const float* __restrict__ x, const float* __restrict__ W,
             const float* __restrict__ bias, const float* __restrict__ gamma,
             const float* __restrict__ beta, float* __restrict__ out) {
    extern __shared__ __align__(16) float dynsm[];
    __shared__ float ys[40 * 16];
    __shared__ float sred[STEPN][16];
    __shared__ float sd[STEPN];
    __shared__ float s_r[8];
    __shared__ float s_tot;

    const int tid = threadIdx.x;
    const int bid = blockIdx.x;

    // ================= phase 1: q rows (blocks 0..79) =================
    if (bid < BS) {
        const int n = bid;
        const int b = n % NBATCH;
        const int s = n / NBATCH;
        const int rb = b * STEPN;

        float pd[STEPN] = {0.f, 0.f, 0.f, 0.f, 0.f};
        const float* xn = x + n * D;
        for (int j = tid; j < D; j += NTHR) {
            float v = xn[j];
#pragma unroll
            for (int t = 0; t < STEPN; t++)
                pd[t] += x[(rb + t) * D + j] * v;
        }
#pragma unroll
        for (int t = 0; t < STEPN; t++) {
            float v = pd[t];
#pragma unroll
            for (int o = 16; o > 0; o >>= 1)
                v += __shfl_down_sync(0xffffffffu, v, o);
            if ((tid & 31) == 0) sred[t][tid >> 5] = v;
        }
        __syncthreads();
        if (tid < STEPN) {
            float v = 0.f;
#pragma unroll
            for (int w = 0; w < 16; w++) v += sred[tid][w];
            sd[tid] = ALPHA * v;
        }
        __syncthreads();
        for (int i = tid; i < D; i += NTHR) {
            float g = 0.f;
            for (int t = 0; t <= s; t++) {
                float xv = x[(rb + t) * D + i];
                g = g * (1.f - ALPHA * xv * xv) + xv * sd[t];
            }
            g_q[n * D + i] = g;
        }
    }

    gridbar(&g_bar0);

    // ================= phase 2: GEMM, smem double-buffered ==================
    // block tile rows [r0,r0+40) x cols [c0,c0+16); 16 warps k-split.
    // warp w covers k = ch*128 + w*8 + [0,8) for ch in 0..7.
    // lane: rg = lane>>2 -> rows rg*5+m; cg = lane&3 -> cols cc*4+cg.
    {
        const int rh = bid >> 6;
        const int r0 = rh * 40;
        const int c0 = (bid & 63) * 16;
        const int w  = tid >> 5;
        const int lane = tid & 31;
        const int rg = lane >> 2;
        const int cg = lane & 3;

        unsigned long long acc[5][4];
#pragma unroll
        for (int m = 0; m < 5; m++)
#pragma unroll
            for (int c = 0; c < 4; c++) acc[m][c] = 0ull;

        // copy-issue for chunk ch into buffer ch&1
        auto issue = [&](int ch) {
            const int kb = ch * 128;
            float* bq = dynsm + (ch & 1) * BUF_FL;
            float* bw = bq + 40 * QW;
#pragma unroll
            for (int i = tid; i < 1792; i += NTHR) {
                if (i < 1280) {
                    int r = i >> 5, v = i & 31;
                    cp_async16(s2u(bq + r * QW + v * 4),
                               g_q + (r0 + r) * D + kb + v * 4);
                } else {
                    int j = i - 1280;
                    int c = j >> 5, v = j & 31;
                    cp_async16(s2u(bw + c * QW + v * 4),
                               W + (c0 + c) * D + kb + v * 4);
                }
            }
            asm volatile("cp.async.commit_group;");
        };

        issue(0);
        for (int ch = 0; ch < 8; ch++) {
            if (ch < 7) {
                issue(ch + 1);
                asm volatile("cp.async.wait_group 1;");
            } else {
                asm volatile("cp.async.wait_group 0;");
            }
            __syncthreads();

            const float* bq = dynsm + (ch & 1) * BUF_FL + (rg * 5) * QW + w * 8;
            const float* bw = dynsm + (ch & 1) * BUF_FL + 40 * QW + cg * QW + w * 8;
#pragma unroll
            for (int qd = 0; qd < 2; qd++) {
                const int k4 = qd * 4;
                ulonglong2 qv[5];
#pragma unroll
                for (int m = 0; m < 5; m++)
                    qv[m] = *(const ulonglong2*)(bq + m * QW + k4);
#pragma unroll
                for (int cc = 0; cc < 4; cc++) {
                    ulonglong2 wv = *(const ulonglong2*)(bw + cc * 4 * QW + k4);
#pragma unroll
                    for (int m = 0; m < 5; m++) {
                        ffma2(acc[m][cc], qv[m].x, wv.x);
                        ffma2(acc[m][cc], qv[m].y, wv.y);
                    }
                }
            }
            __syncthreads();
        }

        // stage folded partials: stg[w*640 + lane*20 + (m*4+cc)]
        float* stg = dynsm;   // buffers dead now
        {
            float* dst = stg + w * 640 + lane * 20;
#pragma unroll
            for (int m = 0; m < 5; m++)
#pragma unroll
                for (int cc = 0; cc < 4; cc++)
                    dst[m * 4 + cc] = fold2(acc[m][cc]);
        }
        __syncthreads();

        // 16-way reduce + bias; write y
        for (int idx = tid; idx < 640; idx += NTHR) {
            const int row = idx >> 4, col = idx & 15;
            const int rg2 = row / 5, m = row - rg2 * 5;
            const int cg2 = col & 3, cc = col >> 2;
            const int off = (rg2 * 4 + cg2) * 20 + m * 4 + cc;
            float s = 0.f;
#pragma unroll
            for (int ww = 0; ww < 16; ww++)
                s += stg[ww * 640 + off];
            const float yv = s + bias[c0 + col];
            g_y[(r0 + row) * D + c0 + col] = yv;
            ys[row * 16 + col] = yv;
        }
        __syncthreads();

        // per-column partial stats over this block's 40 rows
        if (tid < 16) {
            float su = 0.f, sq = 0.f;
#pragma unroll
            for (int r = 0; r < 40; r++) {
                float v = ys[r * 16 + tid];
                su += v;
                sq += v * v;
            }
            g_csum[rh][c0 + tid] = su;
            g_csq[rh][c0 + tid]  = sq;
        }
    }

    gridbar(&g_bar1);

    // ================= phase 3: BN + relu + row L2-normalize =================
    {
        const bool act = (bid < BS) && (tid < 256);
        float z[4];
        float ss = 0.f;
        int k0 = tid * 4;
        if (act) {
            const int n = bid;
            float4 y4  = *(const float4*)(g_y + n * D + k0);
            float4 s04 = *(const float4*)(&g_csum[0][k0]);
            float4 s14 = *(const float4*)(&g_csum[1][k0]);
            float4 q04 = *(const float4*)(&g_csq[0][k0]);
            float4 q14 = *(const float4*)(&g_csq[1][k0]);
            float4 ga4 = *(const float4*)(gamma + k0);
            float4 be4 = *(const float4*)(beta + k0);

            const float inv = 1.f / (float)BS;
            float mu, var, rstd;
            mu = (s04.x + s14.x) * inv; var = (q04.x + q14.x) * inv - mu * mu;
            rstd = rsqrtf(var + 1e-5f);
            z[0] = fmaxf((y4.x - mu) * rstd * ga4.x + be4.x, 0.f);
            mu = (s04.y + s14.y) * inv; var = (q04.y + q14.y) * inv - mu * mu;
            rstd = rsqrtf(var + 1e-5f);
            z[1] = fmaxf((y4.y - mu) * rstd * ga4.y + be4.y, 0.f);
            mu = (s04.z + s14.z) * inv; var = (q04.z + q14.z) * inv - mu * mu;
            rstd = rsqrtf(var + 1e-5f);
            z[2] = fmaxf((y4.z - mu) * rstd * ga4.z + be4.z, 0.f);
            mu = (s04.w + s14.w) * inv; var = (q04.w + q14.w) * inv - mu * mu;
            rstd = rsqrtf(var + 1e-5f);
            z[3] = fmaxf((y4.w - mu) * rstd * ga4.w + be4.w, 0.f);

            ss = z[0] * z[0] + z[1] * z[1] + z[2] * z[2] + z[3] * z[3];
#pragma unroll
            for (int o = 16; o > 0; o >>= 1)
                ss += __shfl_down_sync(0xffffffffu, ss, o);
            if ((tid & 31) == 0) s_r[tid >> 5] = ss;
        }
        __syncthreads();
        if (act && tid == 0) {
            float t = 0.f;
#pragma unroll
            for (int w = 0; w < 8; w++) t += s_r[w];
            s_tot = 1.f / fmaxf(sqrtf(t), 1e-12f);
        }
        __syncthreads();
        if (act) {
            float sc = s_tot;
            float4 o4 = make_float4(z[0] * sc, z[1] * sc, z[2] * sc, z[3] * sc);
            *(float4*)(out + bid * D + k0) = o4;
        }
    }

    // ---- depart + replay-safe reset of barrier state ----
    if (threadIdx.x == 0) {
        __threadfence();
        unsigned old = atomicAdd(&g_depart, 1u);
        if (old == NBLK - 1) {
            g_bar0 = 0;
            g_bar1 = 0;
            __threadfence();
            g_depart = 0;
            __threadfence();
        }
    }
}

extern "C" void kernel_launch(void* const* d_in, const int* in_sizes, int n_in,
                              void* d_out, int out_size) {
    (void)in_sizes; (void)n_in; (void)out_size;
    const float* x     = (const float*)d_in[0];
    const float* W     = (const float*)d_in[1];
    const float* bias  = (const float*)d_in[2];
    const float* gamma = (const float*)d_in[3];
    const float* beta  = (const float*)d_in[4];
    float* out = (float*)d_out;

    static int configured = 0;
    if (!configured) {
        cudaFuncSetAttribute(fused_kernel,
                             cudaFuncAttributeMaxDynamicSharedMemorySize,
                             DYN_FL * (int)sizeof(float));
        configured = 1;
    }
    fused_kernel<<<NBLK, NTHR, DYN_FL * sizeof(float)>>>(x, W, bias, gamma, beta, out);
}